// round 2
// baseline (speedup 1.0000x reference)
#include <cuda_runtime.h>
#include <math.h>

#define H1H 2048          // hidden size for both layers
#define VOC 50257

// Scratch (no allocations allowed)
__device__ float g_h1n[H1H];
__device__ float g_h2n[H1H];
__device__ float g_logits[VOC];
__device__ float g_stats[2];   // [0]=max, [1]=log(sum exp)

// ---------------------------------------------------------------------------
// Fused LSTM layer: one block per hidden unit. Block computes the 4 gate
// dot-products (rows r, r+H, r+2H, r+3H of W_ih and W_hh) against x/h staged
// in shared memory, then applies the LSTM nonlinearity and writes h_new[r].
// Every weight element is read exactly once (float4 vectorized).
// ---------------------------------------------------------------------------
__global__ __launch_bounds__(256) void lstm_layer_kernel(
    const float* __restrict__ Wih, const float* __restrict__ Whh,
    const float* __restrict__ bih, const float* __restrict__ bhh,
    const float* __restrict__ x,  const float* __restrict__ h,
    const float* __restrict__ c,  float* __restrict__ hout, int nx)
{
    __shared__ float sx[2048];
    __shared__ float sh[2048];
    __shared__ float sred[4 * 8];

    const int tid = threadIdx.x;
    for (int i = tid; i < nx;  i += 256) sx[i] = x[i];
    for (int i = tid; i < H1H; i += 256) sh[i] = h[i];
    __syncthreads();

    const int r = blockIdx.x;               // hidden unit index 0..H-1
    const int nx4 = nx >> 2;
    const float4* sx4 = (const float4*)sx;
    const float4* sh4 = (const float4*)sh;

    float acc[4];
    #pragma unroll
    for (int g = 0; g < 4; g++) {
        const size_t row = (size_t)(r + g * H1H);
        const float4* wi = (const float4*)(Wih + row * (size_t)nx);
        const float4* wh = (const float4*)(Whh + row * (size_t)H1H);
        float a = 0.0f;
        for (int j = tid; j < nx4; j += 256) {
            float4 wv = wi[j]; float4 xv = sx4[j];
            a += wv.x * xv.x + wv.y * xv.y + wv.z * xv.z + wv.w * xv.w;
        }
        for (int j = tid; j < (H1H >> 2); j += 256) {
            float4 wv = wh[j]; float4 hv = sh4[j];
            a += wv.x * hv.x + wv.y * hv.y + wv.z * hv.z + wv.w * hv.w;
        }
        acc[g] = a;
    }

    // warp-shuffle reduce, then per-warp partials to shared
    #pragma unroll
    for (int g = 0; g < 4; g++) {
        float a = acc[g];
        #pragma unroll
        for (int o = 16; o > 0; o >>= 1)
            a += __shfl_down_sync(0xffffffffu, a, o);
        if ((tid & 31) == 0) sred[g * 8 + (tid >> 5)] = a;
    }
    __syncthreads();

    if (tid == 0) {
        float gi = 0.f, gf = 0.f, gg = 0.f, go = 0.f;
        #pragma unroll
        for (int w = 0; w < 8; w++) {
            gi += sred[0 * 8 + w];
            gf += sred[1 * 8 + w];
            gg += sred[2 * 8 + w];
            go += sred[3 * 8 + w];
        }
        gi += bih[r]           + bhh[r];
        gf += bih[r + H1H]     + bhh[r + H1H];
        gg += bih[r + 2 * H1H] + bhh[r + 2 * H1H];
        go += bih[r + 3 * H1H] + bhh[r + 3 * H1H];

        const float iv = 1.0f / (1.0f + expf(-gi));
        const float fv = 1.0f / (1.0f + expf(-gf));
        const float gv = tanhf(gg);
        const float ov = 1.0f / (1.0f + expf(-go));
        const float cn = fv * c[r] + iv * gv;
        hout[r] = ov * tanhf(cn);
    }
}

// ---------------------------------------------------------------------------
// Vocab projection: one warp per vocab row, h2n in shared. 16 independent
// float4 loads per lane per row -> deep MLP against DRAM latency.
// ---------------------------------------------------------------------------
__global__ __launch_bounds__(256) void vocab_kernel(
    const float* __restrict__ W, const float* __restrict__ b,
    const float* __restrict__ h, float* __restrict__ logits)
{
    __shared__ float sh[2048];
    const int tid = threadIdx.x;
    for (int i = tid; i < 2048; i += 256) sh[i] = h[i];
    __syncthreads();

    const int warp = blockIdx.x * 8 + (tid >> 5);
    const int lane = tid & 31;
    if (warp >= VOC) return;

    const float4* w4  = (const float4*)(W + (size_t)warp * 2048);
    const float4* sh4 = (const float4*)sh;
    float a = 0.0f;
    #pragma unroll
    for (int j = lane; j < 512; j += 32) {
        float4 wv = w4[j]; float4 hv = sh4[j];
        a += wv.x * hv.x + wv.y * hv.y + wv.z * hv.z + wv.w * hv.w;
    }
    #pragma unroll
    for (int o = 16; o > 0; o >>= 1)
        a += __shfl_down_sync(0xffffffffu, a, o);
    if (lane == 0) logits[warp] = a + b[warp];
}

// ---------------------------------------------------------------------------
// Single-block one-pass online logsumexp over the 50257 logits (L2 resident).
// ---------------------------------------------------------------------------
__global__ __launch_bounds__(1024) void lse_kernel(const float* __restrict__ logits)
{
    __shared__ float sm[1024];
    __shared__ float ss[1024];
    const int tid = threadIdx.x;

    float m = -INFINITY, s = 0.0f;
    for (int i = tid; i < VOC; i += 1024) {
        const float v = logits[i];
        const float nm = fmaxf(m, v);
        s = s * expf(m - nm) + expf(v - nm);
        m = nm;
    }
    sm[tid] = m; ss[tid] = s;
    __syncthreads();
    for (int stride = 512; stride > 0; stride >>= 1) {
        if (tid < stride) {
            const float m2 = sm[tid + stride], s2 = ss[tid + stride];
            const float nm = fmaxf(m, m2);
            s = s * expf(m - nm) + s2 * expf(m2 - nm);
            m = nm;
            sm[tid] = m; ss[tid] = s;
        }
        __syncthreads();
    }
    if (tid == 0) { g_stats[0] = m; g_stats[1] = logf(s); }
}

__global__ __launch_bounds__(256) void finalize_kernel(
    const float* __restrict__ logits, float* __restrict__ out)
{
    const int i = blockIdx.x * 256 + threadIdx.x;
    if (i < VOC) out[i] = logits[i] - g_stats[0] - g_stats[1];
}

// ---------------------------------------------------------------------------
extern "C" void kernel_launch(void* const* d_in, const int* in_sizes, int n_in,
                              void* d_out, int out_size)
{
    const float* x     = (const float*)d_in[0];
    const float* h1    = (const float*)d_in[1];
    const float* c1    = (const float*)d_in[2];
    const float* h2    = (const float*)d_in[3];
    const float* c2    = (const float*)d_in[4];
    const float* W_ih1 = (const float*)d_in[5];
    const float* W_hh1 = (const float*)d_in[6];
    const float* b_ih1 = (const float*)d_in[7];
    const float* b_hh1 = (const float*)d_in[8];
    const float* W_ih2 = (const float*)d_in[9];
    const float* W_hh2 = (const float*)d_in[10];
    const float* b_ih2 = (const float*)d_in[11];
    const float* b_hh2 = (const float*)d_in[12];
    const float* W_out = (const float*)d_in[13];
    const float* b_out = (const float*)d_in[14];
    float* out = (float*)d_out;

    float* h1n;    cudaGetSymbolAddress((void**)&h1n,    g_h1n);
    float* h2n;    cudaGetSymbolAddress((void**)&h2n,    g_h2n);
    float* logits; cudaGetSymbolAddress((void**)&logits, g_logits);

    // Layer 1: x[1024], h1/c1[2048]
    lstm_layer_kernel<<<H1H, 256>>>(W_ih1, W_hh1, b_ih1, b_hh1,
                                    x, h1, c1, h1n, 1024);
    // Layer 2: input = h1n[2048]
    lstm_layer_kernel<<<H1H, 256>>>(W_ih2, W_hh2, b_ih2, b_hh2,
                                    h1n, h2, c2, h2n, 2048);
    // Vocab projection
    vocab_kernel<<<(VOC + 7) / 8, 256>>>(W_out, b_out, h2n, logits);
    // log-softmax
    lse_kernel<<<1, 1024>>>(logits);
    finalize_kernel<<<(VOC + 255) / 256, 256>>>(logits, out);
}

// round 3
// speedup vs baseline: 1.0609x; 1.0609x over previous
#include <cuda_runtime.h>
#include <math.h>

#define H1H 2048          // hidden size for both layers
#define VOC 50257
#define VBLOCKS ((VOC + 7) / 8)   // 6283 vocab blocks, 8 logits each

// Scratch (no allocations allowed)
__device__ float g_h1n[H1H];
__device__ float g_h2n[H1H];
__device__ float g_logits[VOC];
__device__ float g_pm[VBLOCKS];   // per-block partial max
__device__ float g_ps[VBLOCKS];   // per-block partial sum of exp(v - m)
__device__ float g_stats[2];      // [0]=global max, [1]=log(sum exp)

// ---------------------------------------------------------------------------
// Fused LSTM layer: one block per hidden unit. Block computes the 4 gate
// dot-products (rows r, r+H, r+2H, r+3H of W_ih and W_hh) against x/h staged
// in shared memory, then applies the LSTM nonlinearity and writes h_new[r].
// Weights are streamed (touched once) with .cs hint.
// ---------------------------------------------------------------------------
__global__ __launch_bounds__(256) void lstm_layer_kernel(
    const float* __restrict__ Wih, const float* __restrict__ Whh,
    const float* __restrict__ bih, const float* __restrict__ bhh,
    const float* __restrict__ x,  const float* __restrict__ h,
    const float* __restrict__ c,  float* __restrict__ hout, int nx)
{
    __shared__ float sx[2048];
    __shared__ float sh[2048];
    __shared__ float sred[4 * 8];

    const int tid = threadIdx.x;
    for (int i = tid; i < nx;  i += 256) sx[i] = x[i];
    for (int i = tid; i < H1H; i += 256) sh[i] = h[i];
    __syncthreads();

    const int r = blockIdx.x;               // hidden unit index 0..H-1
    const int nx4 = nx >> 2;
    const float4* sx4 = (const float4*)sx;
    const float4* sh4 = (const float4*)sh;

    float acc[4];
    #pragma unroll
    for (int g = 0; g < 4; g++) {
        const size_t row = (size_t)(r + g * H1H);
        const float4* wi = (const float4*)(Wih + row * (size_t)nx);
        const float4* wh = (const float4*)(Whh + row * (size_t)H1H);
        float a = 0.0f;
        for (int j = tid; j < nx4; j += 256) {
            float4 wv = __ldcs(&wi[j]); float4 xv = sx4[j];
            a += wv.x * xv.x + wv.y * xv.y + wv.z * xv.z + wv.w * xv.w;
        }
        for (int j = tid; j < (H1H >> 2); j += 256) {
            float4 wv = __ldcs(&wh[j]); float4 hv = sh4[j];
            a += wv.x * hv.x + wv.y * hv.y + wv.z * hv.z + wv.w * hv.w;
        }
        acc[g] = a;
    }

    // warp-shuffle reduce, then per-warp partials to shared
    #pragma unroll
    for (int g = 0; g < 4; g++) {
        float a = acc[g];
        #pragma unroll
        for (int o = 16; o > 0; o >>= 1)
            a += __shfl_down_sync(0xffffffffu, a, o);
        if ((tid & 31) == 0) sred[g * 8 + (tid >> 5)] = a;
    }
    __syncthreads();

    if (tid == 0) {
        float gi = 0.f, gf = 0.f, gg = 0.f, go = 0.f;
        #pragma unroll
        for (int w = 0; w < 8; w++) {
            gi += sred[0 * 8 + w];
            gf += sred[1 * 8 + w];
            gg += sred[2 * 8 + w];
            go += sred[3 * 8 + w];
        }
        gi += bih[r]           + bhh[r];
        gf += bih[r + H1H]     + bhh[r + H1H];
        gg += bih[r + 2 * H1H] + bhh[r + 2 * H1H];
        go += bih[r + 3 * H1H] + bhh[r + 3 * H1H];

        const float iv = 1.0f / (1.0f + expf(-gi));
        const float fv = 1.0f / (1.0f + expf(-gf));
        const float gv = tanhf(gg);
        const float ov = 1.0f / (1.0f + expf(-go));
        const float cn = fv * c[r] + iv * gv;
        hout[r] = ov * tanhf(cn);
    }
}

// ---------------------------------------------------------------------------
// Vocab projection: one warp per vocab row, h2n in shared. After writing its
// 8 logits, each block also emits a partial (max, sumexp) pair -> the global
// logsumexp then only has to reduce 6283 pairs instead of 50257 logits.
// ---------------------------------------------------------------------------
__global__ __launch_bounds__(256) void vocab_kernel(
    const float* __restrict__ W, const float* __restrict__ b,
    const float* __restrict__ h, float* __restrict__ logits)
{
    __shared__ float sh[2048];
    __shared__ float slog[8];
    const int tid = threadIdx.x;
    for (int i = tid; i < 2048; i += 256) sh[i] = h[i];
    __syncthreads();

    const int wid  = tid >> 5;
    const int lane = tid & 31;
    const int row  = blockIdx.x * 8 + wid;

    float v = -INFINITY;
    if (row < VOC) {
        const float4* w4  = (const float4*)(W + (size_t)row * 2048);
        const float4* sh4 = (const float4*)sh;
        float a = 0.0f;
        #pragma unroll
        for (int j = lane; j < 512; j += 32) {
            float4 wv = __ldcs(&w4[j]); float4 hv = sh4[j];
            a += wv.x * hv.x + wv.y * hv.y + wv.z * hv.z + wv.w * hv.w;
        }
        #pragma unroll
        for (int o = 16; o > 0; o >>= 1)
            a += __shfl_down_sync(0xffffffffu, a, o);
        if (lane == 0) {
            v = a + b[row];
            logits[row] = v;
        }
    }
    if (lane == 0) slog[wid] = v;   // -inf for out-of-range rows
    __syncthreads();

    // one thread folds the block's 8 logits into a partial (m, s)
    if (tid == 0) {
        float m = -INFINITY;
        #pragma unroll
        for (int i = 0; i < 8; i++) m = fmaxf(m, slog[i]);
        float s = 0.0f;
        #pragma unroll
        for (int i = 0; i < 8; i++)
            s += (slog[i] == -INFINITY) ? 0.0f : expf(slog[i] - m);
        g_pm[blockIdx.x] = m;
        g_ps[blockIdx.x] = s;
    }
}

// ---------------------------------------------------------------------------
// Combine 6283 partial (m, s) pairs into global (max, log-sum-exp). 50 KB of
// L2-resident data, one block, ~2-3 us.
// ---------------------------------------------------------------------------
__global__ __launch_bounds__(1024) void lse_combine_kernel()
{
    __shared__ float sm[1024];
    __shared__ float ss[1024];
    const int tid = threadIdx.x;

    float m = -INFINITY, s = 0.0f;
    for (int i = tid; i < VBLOCKS; i += 1024) {
        const float m2 = g_pm[i], s2 = g_ps[i];
        const float nm = fmaxf(m, m2);
        s = s * expf(m - nm) + s2 * expf(m2 - nm);
        m = nm;
    }
    sm[tid] = m; ss[tid] = s;
    __syncthreads();
    for (int stride = 512; stride > 0; stride >>= 1) {
        if (tid < stride) {
            const float m2 = sm[tid + stride], s2 = ss[tid + stride];
            const float nm = fmaxf(m, m2);
            s = s * expf(m - nm) + s2 * expf(m2 - nm);
            m = nm;
            sm[tid] = m; ss[tid] = s;
        }
        __syncthreads();
    }
    if (tid == 0) { g_stats[0] = m; g_stats[1] = logf(s); }
}

__global__ __launch_bounds__(256) void finalize_kernel(
    const float* __restrict__ logits, float* __restrict__ out)
{
    const int i = blockIdx.x * 256 + threadIdx.x;
    if (i < VOC) out[i] = logits[i] - g_stats[0] - g_stats[1];
}

// ---------------------------------------------------------------------------
extern "C" void kernel_launch(void* const* d_in, const int* in_sizes, int n_in,
                              void* d_out, int out_size)
{
    const float* x     = (const float*)d_in[0];
    const float* h1    = (const float*)d_in[1];
    const float* c1    = (const float*)d_in[2];
    const float* h2    = (const float*)d_in[3];
    const float* c2    = (const float*)d_in[4];
    const float* W_ih1 = (const float*)d_in[5];
    const float* W_hh1 = (const float*)d_in[6];
    const float* b_ih1 = (const float*)d_in[7];
    const float* b_hh1 = (const float*)d_in[8];
    const float* W_ih2 = (const float*)d_in[9];
    const float* W_hh2 = (const float*)d_in[10];
    const float* b_ih2 = (const float*)d_in[11];
    const float* b_hh2 = (const float*)d_in[12];
    const float* W_out = (const float*)d_in[13];
    const float* b_out = (const float*)d_in[14];
    float* out = (float*)d_out;

    float* h1n;    cudaGetSymbolAddress((void**)&h1n,    g_h1n);
    float* h2n;    cudaGetSymbolAddress((void**)&h2n,    g_h2n);
    float* logits; cudaGetSymbolAddress((void**)&logits, g_logits);

    // Layer 1: x[1024], h1/c1[2048]
    lstm_layer_kernel<<<H1H, 256>>>(W_ih1, W_hh1, b_ih1, b_hh1,
                                    x, h1, c1, h1n, 1024);
    // Layer 2: input = h1n[2048]
    lstm_layer_kernel<<<H1H, 256>>>(W_ih2, W_hh2, b_ih2, b_hh2,
                                    h1n, h2, c2, h2n, 2048);
    // Vocab projection + per-block lse partials
    vocab_kernel<<<VBLOCKS, 256>>>(W_out, b_out, h2n, logits);
    // Combine partials -> global (max, log-sum-exp)
    lse_combine_kernel<<<1, 1024>>>();
    // log-softmax output
    finalize_kernel<<<(VOC + 255) / 256, 256>>>(logits, out);
}

// round 4
// speedup vs baseline: 1.0969x; 1.0339x over previous
#include <cuda_runtime.h>
#include <math.h>

#define H1H 2048          // hidden size for both layers
#define VOC 50257

#define VBLK 592          // persistent vocab blocks (<= 152 SMs * 4 resident)
#define VTHR 256          // threads per vocab block
#define VWARPS_TOTAL (VBLK * (VTHR / 32))   // 4736 warps == rows per sweep
#define VITERS ((VOC + VWARPS_TOTAL - 1) / VWARPS_TOTAL)  // 11

// Scratch (no allocations allowed)
__device__ float g_h1n[H1H];
__device__ float g_h2n[H1H];
__device__ float g_logits[VOC];
__device__ float g_pm[VBLK];                 // per-block partial max
__device__ float g_ps[VBLK];                 // per-block partial sum exp(v-m)
__device__ unsigned long long g_ticket = 0;  // monotonic grid barrier (replay-safe)

// ---------------------------------------------------------------------------
// Fused LSTM layer: one block per hidden unit. Block computes the 4 gate
// dot-products (rows r, r+H, r+2H, r+3H of W_ih and W_hh) against x/h staged
// in shared memory, then applies the LSTM nonlinearity and writes h_new[r].
// ---------------------------------------------------------------------------
__global__ __launch_bounds__(256) void lstm_layer_kernel(
    const float* __restrict__ Wih, const float* __restrict__ Whh,
    const float* __restrict__ bih, const float* __restrict__ bhh,
    const float* __restrict__ x,  const float* __restrict__ h,
    const float* __restrict__ c,  float* __restrict__ hout, int nx)
{
    __shared__ float sx[2048];
    __shared__ float sh[2048];
    __shared__ float sred[4 * 8];

    const int tid = threadIdx.x;
    for (int i = tid; i < nx;  i += 256) sx[i] = x[i];
    for (int i = tid; i < H1H; i += 256) sh[i] = h[i];
    __syncthreads();

    const int r = blockIdx.x;
    const int nx4 = nx >> 2;
    const float4* sx4 = (const float4*)sx;
    const float4* sh4 = (const float4*)sh;

    float acc[4];
    #pragma unroll
    for (int g = 0; g < 4; g++) {
        const size_t row = (size_t)(r + g * H1H);
        const float4* wi = (const float4*)(Wih + row * (size_t)nx);
        const float4* wh = (const float4*)(Whh + row * (size_t)H1H);
        float a = 0.0f;
        for (int j = tid; j < nx4; j += 256) {
            float4 wv = __ldcs(&wi[j]); float4 xv = sx4[j];
            a += wv.x * xv.x + wv.y * xv.y + wv.z * xv.z + wv.w * xv.w;
        }
        for (int j = tid; j < (H1H >> 2); j += 256) {
            float4 wv = __ldcs(&wh[j]); float4 hv = sh4[j];
            a += wv.x * hv.x + wv.y * hv.y + wv.z * hv.z + wv.w * hv.w;
        }
        acc[g] = a;
    }

    #pragma unroll
    for (int g = 0; g < 4; g++) {
        float a = acc[g];
        #pragma unroll
        for (int o = 16; o > 0; o >>= 1)
            a += __shfl_down_sync(0xffffffffu, a, o);
        if ((tid & 31) == 0) sred[g * 8 + (tid >> 5)] = a;
    }
    __syncthreads();

    if (tid == 0) {
        float gi = 0.f, gf = 0.f, gg = 0.f, go = 0.f;
        #pragma unroll
        for (int w = 0; w < 8; w++) {
            gi += sred[0 * 8 + w];
            gf += sred[1 * 8 + w];
            gg += sred[2 * 8 + w];
            go += sred[3 * 8 + w];
        }
        gi += bih[r]           + bhh[r];
        gf += bih[r + H1H]     + bhh[r + H1H];
        gg += bih[r + 2 * H1H] + bhh[r + 2 * H1H];
        go += bih[r + 3 * H1H] + bhh[r + 3 * H1H];

        const float iv = 1.0f / (1.0f + expf(-gi));
        const float fv = 1.0f / (1.0f + expf(-gf));
        const float gv = tanhf(gg);
        const float ov = 1.0f / (1.0f + expf(-go));
        const float cn = fv * c[r] + iv * gv;
        hout[r] = ov * tanhf(cn);
    }
}

// ---------------------------------------------------------------------------
// Persistent fused vocab kernel: GEMV logits + logsumexp + log-softmax output,
// all in one launch. Grid is fully co-resident (592 blocks, <=4/SM), so a
// hand-rolled grid barrier is safe. The monotonic 64-bit ticket counter makes
// the barrier correct across unlimited graph replays with no reset step.
// ---------------------------------------------------------------------------
__global__ __launch_bounds__(VTHR, 4) void vocab_fused_kernel(
    const float* __restrict__ W, const float* __restrict__ b,
    const float* __restrict__ h, float* __restrict__ out)
{
    __shared__ float sh[2048];
    __shared__ float swm[8];     // per-warp max
    __shared__ float sws[8];     // per-warp sumexp
    __shared__ float sred[256];  // generic block reduce

    const int tid  = threadIdx.x;
    const int wid  = tid >> 5;
    const int lane = tid & 31;
    const int wglob = blockIdx.x * 8 + wid;   // global warp id == row stride base

    for (int i = tid; i < 2048; i += VTHR) sh[i] = h[i];
    __syncthreads();

    const float4* sh4 = (const float4*)sh;

    // ---- phase 1: rows, with per-warp online (m, s) ----
    float m = -INFINITY, s = 0.0f;
    for (int it = 0; it < VITERS; it++) {
        const int row = wglob + it * VWARPS_TOTAL;
        if (row < VOC) {
            const float4* w4 = (const float4*)(W + (size_t)row * 2048);
            float a = 0.0f;
            #pragma unroll 8
            for (int j = lane; j < 512; j += 32) {
                float4 wv = __ldcs(&w4[j]); float4 hv = sh4[j];
                a += wv.x * hv.x + wv.y * hv.y + wv.z * hv.z + wv.w * hv.w;
            }
            #pragma unroll
            for (int o = 16; o > 0; o >>= 1)
                a += __shfl_xor_sync(0xffffffffu, a, o);
            const float v = a + __ldg(&b[row]);       // all lanes hold v
            if (lane == 0) g_logits[row] = v;
            // online update (redundant across lanes, keeps warp converged)
            const float nm = fmaxf(m, v);
            s = s * expf(m - nm) + expf(v - nm);
            m = nm;
        }
    }
    if (lane == 0) { swm[wid] = m; sws[wid] = s; }
    __syncthreads();

    // ---- phase 2: block partial (m, s) -> global scratch ----
    if (tid == 0) {
        float bm = -INFINITY;
        #pragma unroll
        for (int i = 0; i < 8; i++) bm = fmaxf(bm, swm[i]);
        float bs = 0.0f;
        #pragma unroll
        for (int i = 0; i < 8; i++)
            bs += (swm[i] == -INFINITY) ? 0.0f : sws[i] * expf(swm[i] - bm);
        g_pm[blockIdx.x] = bm;
        g_ps[blockIdx.x] = bs;
    }

    // ---- phase 3: grid barrier (monotonic ticket, replay-safe) ----
    __threadfence();
    __syncthreads();
    if (tid == 0) {
        const unsigned long long my = atomicAdd(&g_ticket, 1ULL);
        const unsigned long long target = (my / VBLK + 1ULL) * VBLK;
        while (atomicAdd(&g_ticket, 0ULL) < target) { }
    }
    __syncthreads();
    __threadfence();

    // ---- phase 4: every block redundantly reduces the 592 partials ----
    float lm = -INFINITY;
    for (int i = tid; i < VBLK; i += VTHR) lm = fmaxf(lm, g_pm[i]);
    sred[tid] = lm;
    __syncthreads();
    for (int st = 128; st > 0; st >>= 1) {
        if (tid < st) sred[tid] = fmaxf(sred[tid], sred[tid + st]);
        __syncthreads();
    }
    const float M = sred[0];
    __syncthreads();

    float ls = 0.0f;
    for (int i = tid; i < VBLK; i += VTHR)
        ls += (g_pm[i] == -INFINITY) ? 0.0f : g_ps[i] * expf(g_pm[i] - M);
    sred[tid] = ls;
    __syncthreads();
    for (int st = 128; st > 0; st >>= 1) {
        if (tid < st) sred[tid] += sred[tid + st];
        __syncthreads();
    }
    const float shift = M + logf(sred[0]);

    // ---- phase 5: write log-softmax output ----
    for (int i = blockIdx.x * VTHR + tid; i < VOC; i += VBLK * VTHR)
        out[i] = g_logits[i] - shift;
}

// ---------------------------------------------------------------------------
extern "C" void kernel_launch(void* const* d_in, const int* in_sizes, int n_in,
                              void* d_out, int out_size)
{
    const float* x     = (const float*)d_in[0];
    const float* h1    = (const float*)d_in[1];
    const float* c1    = (const float*)d_in[2];
    const float* h2    = (const float*)d_in[3];
    const float* c2    = (const float*)d_in[4];
    const float* W_ih1 = (const float*)d_in[5];
    const float* W_hh1 = (const float*)d_in[6];
    const float* b_ih1 = (const float*)d_in[7];
    const float* b_hh1 = (const float*)d_in[8];
    const float* W_ih2 = (const float*)d_in[9];
    const float* W_hh2 = (const float*)d_in[10];
    const float* b_ih2 = (const float*)d_in[11];
    const float* b_hh2 = (const float*)d_in[12];
    const float* W_out = (const float*)d_in[13];
    const float* b_out = (const float*)d_in[14];
    float* out = (float*)d_out;

    float* h1n; cudaGetSymbolAddress((void**)&h1n, g_h1n);
    float* h2n; cudaGetSymbolAddress((void**)&h2n, g_h2n);

    // Layer 1: x[1024], h1/c1[2048]
    lstm_layer_kernel<<<H1H, 256>>>(W_ih1, W_hh1, b_ih1, b_hh1,
                                    x, h1, c1, h1n, 1024);
    // Layer 2: input = h1n[2048]
    lstm_layer_kernel<<<H1H, 256>>>(W_ih2, W_hh2, b_ih2, b_hh2,
                                    h1n, h2, c2, h2n, 2048);
    // Persistent fused vocab projection + logsumexp + log-softmax
    vocab_fused_kernel<<<VBLK, VTHR>>>(W_out, b_out, h2n, out);
}

// round 5
// speedup vs baseline: 1.1663x; 1.0633x over previous
#include <cuda_runtime.h>
#include <math.h>

#define H 2048            // hidden size for both layers
#define VOC 50257

#define VBLK 592          // persistent vocab blocks (<= 152 SMs * 4 resident)
#define VTHR 256
#define VWARPS_TOTAL (VBLK * (VTHR / 32))   // 4736 warps per sweep
#define VITERS ((VOC + VWARPS_TOTAL - 1) / VWARPS_TOTAL)  // 11

// Scratch (no allocations allowed)
__device__ float g_h1n[H];
__device__ float g_h2n[H];
__device__ float g_gates2[4 * H];            // W_hh2@h2 + b_ih2 + b_hh2 (partial)
__device__ float g_logits[VOC];
__device__ float g_pm[VBLK];
__device__ float g_ps[VBLK];
__device__ unsigned long long g_ticket = 0;  // monotonic grid barrier (replay-safe)

__device__ __forceinline__ float warp_sum(float a) {
    #pragma unroll
    for (int o = 16; o > 0; o >>= 1)
        a += __shfl_xor_sync(0xffffffffu, a, o);
    return a;
}

__device__ __forceinline__ float sigmoidf_(float v) {
    return 1.0f / (1.0f + expf(-v));
}

// ---------------------------------------------------------------------------
// Stage A (512 blocks):
//   blocks [0,256):   full layer-1 LSTM cell, warp-per-hidden-unit.
//   blocks [256,512): hh2 partial: gates2[r + g*H] = W_hh2[row]·h2 + b_ih2+b_hh2
// The two halves are independent and stream 168 MB of weights concurrently.
// ---------------------------------------------------------------------------
__global__ __launch_bounds__(256) void stageA_kernel(
    const float* __restrict__ W_ih1, const float* __restrict__ W_hh1,
    const float* __restrict__ b_ih1, const float* __restrict__ b_hh1,
    const float* __restrict__ x,     const float* __restrict__ h1,
    const float* __restrict__ c1,
    const float* __restrict__ W_hh2, const float* __restrict__ b_ih2,
    const float* __restrict__ b_hh2, const float* __restrict__ h2)
{
    __shared__ float sbuf[3072];
    const int tid  = threadIdx.x;
    const int wid  = tid >> 5;
    const int lane = tid & 31;

    if (blockIdx.x < 256) {
        // ---------------- layer 1 ----------------
        float* sx = sbuf;            // x: 1024
        float* sh = sbuf + 1024;     // h1: 2048
        for (int i = tid; i < 1024; i += 256) sx[i] = x[i];
        for (int i = tid; i < 2048; i += 256) sh[i] = h1[i];
        __syncthreads();

        const int r = blockIdx.x * 8 + wid;   // hidden unit
        const float4* sx4 = (const float4*)sx;
        const float4* sh4 = (const float4*)sh;

        // 4 gate rows interleaved -> 4 independent load streams per lane
        const float4* wi0 = (const float4*)(W_ih1 + (size_t)(r        ) * 1024);
        const float4* wi1 = (const float4*)(W_ih1 + (size_t)(r +     H) * 1024);
        const float4* wi2 = (const float4*)(W_ih1 + (size_t)(r + 2 * H) * 1024);
        const float4* wi3 = (const float4*)(W_ih1 + (size_t)(r + 3 * H) * 1024);
        const float4* wh0 = (const float4*)(W_hh1 + (size_t)(r        ) * 2048);
        const float4* wh1 = (const float4*)(W_hh1 + (size_t)(r +     H) * 2048);
        const float4* wh2 = (const float4*)(W_hh1 + (size_t)(r + 2 * H) * 2048);
        const float4* wh3 = (const float4*)(W_hh1 + (size_t)(r + 3 * H) * 2048);

        float a0 = 0.f, a1 = 0.f, a2 = 0.f, a3 = 0.f;
        #pragma unroll 2
        for (int j = lane; j < 256; j += 32) {
            const float4 xv = sx4[j];
            const float4 p0 = __ldcs(&wi0[j]);
            const float4 p1 = __ldcs(&wi1[j]);
            const float4 p2 = __ldcs(&wi2[j]);
            const float4 p3 = __ldcs(&wi3[j]);
            a0 += p0.x*xv.x + p0.y*xv.y + p0.z*xv.z + p0.w*xv.w;
            a1 += p1.x*xv.x + p1.y*xv.y + p1.z*xv.z + p1.w*xv.w;
            a2 += p2.x*xv.x + p2.y*xv.y + p2.z*xv.z + p2.w*xv.w;
            a3 += p3.x*xv.x + p3.y*xv.y + p3.z*xv.z + p3.w*xv.w;
        }
        #pragma unroll 2
        for (int j = lane; j < 512; j += 32) {
            const float4 hv = sh4[j];
            const float4 p0 = __ldcs(&wh0[j]);
            const float4 p1 = __ldcs(&wh1[j]);
            const float4 p2 = __ldcs(&wh2[j]);
            const float4 p3 = __ldcs(&wh3[j]);
            a0 += p0.x*hv.x + p0.y*hv.y + p0.z*hv.z + p0.w*hv.w;
            a1 += p1.x*hv.x + p1.y*hv.y + p1.z*hv.z + p1.w*hv.w;
            a2 += p2.x*hv.x + p2.y*hv.y + p2.z*hv.z + p2.w*hv.w;
            a3 += p3.x*hv.x + p3.y*hv.y + p3.z*hv.z + p3.w*hv.w;
        }
        a0 = warp_sum(a0); a1 = warp_sum(a1); a2 = warp_sum(a2); a3 = warp_sum(a3);

        if (lane == 0) {
            const float gi = a0 + b_ih1[r        ] + b_hh1[r        ];
            const float gf = a1 + b_ih1[r +     H] + b_hh1[r +     H];
            const float gg = a2 + b_ih1[r + 2 * H] + b_hh1[r + 2 * H];
            const float go = a3 + b_ih1[r + 3 * H] + b_hh1[r + 3 * H];
            const float iv = sigmoidf_(gi);
            const float fv = sigmoidf_(gf);
            const float gv = tanhf(gg);
            const float ov = sigmoidf_(go);
            const float cn = fv * c1[r] + iv * gv;
            g_h1n[r] = ov * tanhf(cn);
        }
    } else {
        // ---------------- hh2 gate partials ----------------
        float* sh = sbuf;            // h2: 2048
        for (int i = tid; i < 2048; i += 256) sh[i] = h2[i];
        __syncthreads();

        const int r = (blockIdx.x - 256) * 8 + wid;
        const float4* sh4 = (const float4*)sh;
        const float4* w0 = (const float4*)(W_hh2 + (size_t)(r        ) * 2048);
        const float4* w1 = (const float4*)(W_hh2 + (size_t)(r +     H) * 2048);
        const float4* w2 = (const float4*)(W_hh2 + (size_t)(r + 2 * H) * 2048);
        const float4* w3 = (const float4*)(W_hh2 + (size_t)(r + 3 * H) * 2048);

        float a0 = 0.f, a1 = 0.f, a2 = 0.f, a3 = 0.f;
        #pragma unroll 2
        for (int j = lane; j < 512; j += 32) {
            const float4 hv = sh4[j];
            const float4 p0 = __ldcs(&w0[j]);
            const float4 p1 = __ldcs(&w1[j]);
            const float4 p2 = __ldcs(&w2[j]);
            const float4 p3 = __ldcs(&w3[j]);
            a0 += p0.x*hv.x + p0.y*hv.y + p0.z*hv.z + p0.w*hv.w;
            a1 += p1.x*hv.x + p1.y*hv.y + p1.z*hv.z + p1.w*hv.w;
            a2 += p2.x*hv.x + p2.y*hv.y + p2.z*hv.z + p2.w*hv.w;
            a3 += p3.x*hv.x + p3.y*hv.y + p3.z*hv.z + p3.w*hv.w;
        }
        a0 = warp_sum(a0); a1 = warp_sum(a1); a2 = warp_sum(a2); a3 = warp_sum(a3);

        if (lane == 0) {
            g_gates2[r        ] = a0 + b_ih2[r        ] + b_hh2[r        ];
            g_gates2[r +     H] = a1 + b_ih2[r +     H] + b_hh2[r +     H];
            g_gates2[r + 2 * H] = a2 + b_ih2[r + 2 * H] + b_hh2[r + 2 * H];
            g_gates2[r + 3 * H] = a3 + b_ih2[r + 3 * H] + b_hh2[r + 3 * H];
        }
    }
}

// ---------------------------------------------------------------------------
// Stage B (256 blocks): finish layer 2. Warp-per-unit: 4 rows of W_ih2 · h1n,
// add precomputed hh2 partials, apply LSTM cell with c2 -> g_h2n.
// ---------------------------------------------------------------------------
__global__ __launch_bounds__(256) void stageB_kernel(
    const float* __restrict__ W_ih2, const float* __restrict__ c2)
{
    __shared__ float sh[2048];
    const int tid  = threadIdx.x;
    const int wid  = tid >> 5;
    const int lane = tid & 31;

    for (int i = tid; i < 2048; i += 256) sh[i] = g_h1n[i];
    __syncthreads();

    const int r = blockIdx.x * 8 + wid;
    const float4* sh4 = (const float4*)sh;
    const float4* w0 = (const float4*)(W_ih2 + (size_t)(r        ) * 2048);
    const float4* w1 = (const float4*)(W_ih2 + (size_t)(r +     H) * 2048);
    const float4* w2 = (const float4*)(W_ih2 + (size_t)(r + 2 * H) * 2048);
    const float4* w3 = (const float4*)(W_ih2 + (size_t)(r + 3 * H) * 2048);

    float a0 = 0.f, a1 = 0.f, a2 = 0.f, a3 = 0.f;
    #pragma unroll 2
    for (int j = lane; j < 512; j += 32) {
        const float4 hv = sh4[j];
        const float4 p0 = __ldcs(&w0[j]);
        const float4 p1 = __ldcs(&w1[j]);
        const float4 p2 = __ldcs(&w2[j]);
        const float4 p3 = __ldcs(&w3[j]);
        a0 += p0.x*hv.x + p0.y*hv.y + p0.z*hv.z + p0.w*hv.w;
        a1 += p1.x*hv.x + p1.y*hv.y + p1.z*hv.z + p1.w*hv.w;
        a2 += p2.x*hv.x + p2.y*hv.y + p2.z*hv.z + p2.w*hv.w;
        a3 += p3.x*hv.x + p3.y*hv.y + p3.z*hv.z + p3.w*hv.w;
    }
    a0 = warp_sum(a0); a1 = warp_sum(a1); a2 = warp_sum(a2); a3 = warp_sum(a3);

    if (lane == 0) {
        const float gi = a0 + g_gates2[r        ];
        const float gf = a1 + g_gates2[r +     H];
        const float gg = a2 + g_gates2[r + 2 * H];
        const float go = a3 + g_gates2[r + 3 * H];
        const float iv = sigmoidf_(gi);
        const float fv = sigmoidf_(gf);
        const float gv = tanhf(gg);
        const float ov = sigmoidf_(go);
        const float cn = fv * c2[r] + iv * gv;
        g_h2n[r] = ov * tanhf(cn);
    }
}

// ---------------------------------------------------------------------------
// Persistent fused vocab kernel: GEMV logits + logsumexp + log-softmax output.
// Grid fully co-resident (592 blocks, <=4/SM); monotonic ticket barrier is
// replay-safe with no reset step.
// ---------------------------------------------------------------------------
__global__ __launch_bounds__(VTHR, 4) void vocab_fused_kernel(
    const float* __restrict__ W, const float* __restrict__ b,
    float* __restrict__ out)
{
    __shared__ float sh[2048];
    __shared__ float swm[8];
    __shared__ float sws[8];
    __shared__ float sred[256];

    const int tid  = threadIdx.x;
    const int wid  = tid >> 5;
    const int lane = tid & 31;
    const int wglob = blockIdx.x * 8 + wid;

    for (int i = tid; i < 2048; i += VTHR) sh[i] = g_h2n[i];
    __syncthreads();

    const float4* sh4 = (const float4*)sh;

    float m = -INFINITY, s = 0.0f;
    for (int it = 0; it < VITERS; it++) {
        const int row = wglob + it * VWARPS_TOTAL;
        if (row < VOC) {
            const float4* w4 = (const float4*)(W + (size_t)row * 2048);
            float a = 0.0f;
            #pragma unroll 8
            for (int j = lane; j < 512; j += 32) {
                float4 wv = __ldcs(&w4[j]); float4 hv = sh4[j];
                a += wv.x * hv.x + wv.y * hv.y + wv.z * hv.z + wv.w * hv.w;
            }
            a = warp_sum(a);
            const float v = a + __ldg(&b[row]);
            if (lane == 0) g_logits[row] = v;
            const float nm = fmaxf(m, v);
            s = s * expf(m - nm) + expf(v - nm);
            m = nm;
        }
    }
    if (lane == 0) { swm[wid] = m; sws[wid] = s; }
    __syncthreads();

    if (tid == 0) {
        float bm = -INFINITY;
        #pragma unroll
        for (int i = 0; i < 8; i++) bm = fmaxf(bm, swm[i]);
        float bs = 0.0f;
        #pragma unroll
        for (int i = 0; i < 8; i++)
            bs += (swm[i] == -INFINITY) ? 0.0f : sws[i] * expf(swm[i] - bm);
        g_pm[blockIdx.x] = bm;
        g_ps[blockIdx.x] = bs;
    }

    __threadfence();
    __syncthreads();
    if (tid == 0) {
        const unsigned long long my = atomicAdd(&g_ticket, 1ULL);
        const unsigned long long target = (my / VBLK + 1ULL) * VBLK;
        while (atomicAdd(&g_ticket, 0ULL) < target) { }
    }
    __syncthreads();
    __threadfence();

    float lm = -INFINITY;
    for (int i = tid; i < VBLK; i += VTHR) lm = fmaxf(lm, g_pm[i]);
    sred[tid] = lm;
    __syncthreads();
    for (int st = 128; st > 0; st >>= 1) {
        if (tid < st) sred[tid] = fmaxf(sred[tid], sred[tid + st]);
        __syncthreads();
    }
    const float M = sred[0];
    __syncthreads();

    float ls = 0.0f;
    for (int i = tid; i < VBLK; i += VTHR)
        ls += (g_pm[i] == -INFINITY) ? 0.0f : g_ps[i] * expf(g_pm[i] - M);
    sred[tid] = ls;
    __syncthreads();
    for (int st = 128; st > 0; st >>= 1) {
        if (tid < st) sred[tid] += sred[tid + st];
        __syncthreads();
    }
    const float shift = M + logf(sred[0]);

    for (int i = blockIdx.x * VTHR + tid; i < VOC; i += VBLK * VTHR)
        out[i] = g_logits[i] - shift;
}

// ---------------------------------------------------------------------------
extern "C" void kernel_launch(void* const* d_in, const int* in_sizes, int n_in,
                              void* d_out, int out_size)
{
    const float* x     = (const float*)d_in[0];
    const float* h1    = (const float*)d_in[1];
    const float* c1    = (const float*)d_in[2];
    const float* h2    = (const float*)d_in[3];
    const float* c2    = (const float*)d_in[4];
    const float* W_ih1 = (const float*)d_in[5];
    const float* W_hh1 = (const float*)d_in[6];
    const float* b_ih1 = (const float*)d_in[7];
    const float* b_hh1 = (const float*)d_in[8];
    const float* W_ih2 = (const float*)d_in[9];
    const float* W_hh2 = (const float*)d_in[10];
    const float* b_ih2 = (const float*)d_in[11];
    const float* b_hh2 = (const float*)d_in[12];
    const float* W_out = (const float*)d_in[13];
    const float* b_out = (const float*)d_in[14];
    float* out = (float*)d_out;

    // Stage A: layer 1 LSTM + layer 2 hh-partial (independent, concurrent)
    stageA_kernel<<<512, 256>>>(W_ih1, W_hh1, b_ih1, b_hh1, x, h1, c1,
                                W_hh2, b_ih2, b_hh2, h2);
    // Stage B: finish layer 2 (ih part + cell)
    stageB_kernel<<<256, 256>>>(W_ih2, c2);
    // Persistent fused vocab projection + logsumexp + log-softmax
    vocab_fused_kernel<<<VBLK, VTHR>>>(W_out, b_out, out);
}

// round 6
// speedup vs baseline: 1.2458x; 1.0682x over previous
#include <cuda_runtime.h>
#include <math.h>

#define H 2048            // hidden size for both layers
#define VOC 50257

#define VBLK 592          // persistent vocab blocks (<= 148 SMs * 4 resident)
#define VTHR 256
#define VWARPS_TOTAL (VBLK * (VTHR / 32))   // 4736 warps per sweep
#define VITERS ((VOC + VWARPS_TOTAL - 1) / VWARPS_TOTAL)  // 11

// Scratch (no allocations allowed)
__device__ float g_h1n[H];
__device__ float g_h2n[H];
__device__ float g_gates2[4 * H];            // W_hh2@h2 + b_ih2 + b_hh2 (partial)
__device__ float g_logits[VOC];
__device__ float g_pm[VBLK];
__device__ float g_ps[VBLK];
__device__ unsigned long long g_ticket = 0;  // monotonic grid barrier (replay-safe)

__device__ __forceinline__ float warp_sum(float a) {
    #pragma unroll
    for (int o = 16; o > 0; o >>= 1)
        a += __shfl_xor_sync(0xffffffffu, a, o);
    return a;
}

__device__ __forceinline__ float sigmoidf_(float v) {
    return 1.0f / (1.0f + expf(-v));
}

// 4-row-stream partial dot over [j0, j0+cnt) float4's of K.
// w0..w3 are the 4 gate-row base pointers, v4 the staged vector.
__device__ __forceinline__ void dot4_range(
    const float4* __restrict__ w0, const float4* __restrict__ w1,
    const float4* __restrict__ w2, const float4* __restrict__ w3,
    const float4* __restrict__ v4, int j0, int cnt, int lane,
    float& a0, float& a1, float& a2, float& a3)
{
    #pragma unroll 4
    for (int t = 0; t < cnt / 32; t++) {
        const int j = j0 + lane + t * 32;
        const float4 vv = v4[j];
        const float4 p0 = __ldcs(&w0[j]);
        const float4 p1 = __ldcs(&w1[j]);
        const float4 p2 = __ldcs(&w2[j]);
        const float4 p3 = __ldcs(&w3[j]);
        a0 += p0.x*vv.x + p0.y*vv.y + p0.z*vv.z + p0.w*vv.w;
        a1 += p1.x*vv.x + p1.y*vv.y + p1.z*vv.z + p1.w*vv.w;
        a2 += p2.x*vv.x + p2.y*vv.y + p2.z*vv.z + p2.w*vv.w;
        a3 += p3.x*vv.x + p3.y*vv.y + p3.z*vv.z + p3.w*vv.w;
    }
}

// ---------------------------------------------------------------------------
// Stage A (1024 blocks x 256 thr): 2 warps per hidden unit (K-split halves).
//   blocks [0,512):    layer-1 LSTM cell (4 units/block)
//   blocks [512,1024): W_hh2@h2 + biases partial (4 units/block)
// ---------------------------------------------------------------------------
__global__ __launch_bounds__(256) void stageA_kernel(
    const float* __restrict__ W_ih1, const float* __restrict__ W_hh1,
    const float* __restrict__ b_ih1, const float* __restrict__ b_hh1,
    const float* __restrict__ x,     const float* __restrict__ h1,
    const float* __restrict__ c1,
    const float* __restrict__ W_hh2, const float* __restrict__ b_ih2,
    const float* __restrict__ b_hh2, const float* __restrict__ h2)
{
    __shared__ float sbuf[3072];
    __shared__ float sred[4 * 2 * 4];   // [unit][half][gate]
    const int tid  = threadIdx.x;
    const int wid  = tid >> 5;
    const int lane = tid & 31;
    const int uw   = wid & 3;           // unit within block
    const int half = wid >> 2;          // K-half this warp owns

    if (blockIdx.x < 512) {
        // ---------------- layer 1 ----------------
        float* sx = sbuf;               // x: 1024
        float* sh = sbuf + 1024;        // h1: 2048
        for (int i = tid; i < 1024; i += 256) sx[i] = x[i];
        for (int i = tid; i < 2048; i += 256) sh[i] = h1[i];
        __syncthreads();

        const int r = blockIdx.x * 4 + uw;
        const float4* sx4 = (const float4*)sx;
        const float4* sh4 = (const float4*)sh;

        const float4* wi0 = (const float4*)(W_ih1 + (size_t)(r        ) * 1024);
        const float4* wi1 = (const float4*)(W_ih1 + (size_t)(r +     H) * 1024);
        const float4* wi2 = (const float4*)(W_ih1 + (size_t)(r + 2 * H) * 1024);
        const float4* wi3 = (const float4*)(W_ih1 + (size_t)(r + 3 * H) * 1024);
        const float4* wh0 = (const float4*)(W_hh1 + (size_t)(r        ) * 2048);
        const float4* wh1 = (const float4*)(W_hh1 + (size_t)(r +     H) * 2048);
        const float4* wh2 = (const float4*)(W_hh1 + (size_t)(r + 2 * H) * 2048);
        const float4* wh3 = (const float4*)(W_hh1 + (size_t)(r + 3 * H) * 2048);

        float a0 = 0.f, a1 = 0.f, a2 = 0.f, a3 = 0.f;
        dot4_range(wi0, wi1, wi2, wi3, sx4, half * 128, 128, lane, a0, a1, a2, a3);
        dot4_range(wh0, wh1, wh2, wh3, sh4, half * 256, 256, lane, a0, a1, a2, a3);
        a0 = warp_sum(a0); a1 = warp_sum(a1); a2 = warp_sum(a2); a3 = warp_sum(a3);

        if (lane == 0) {
            float* d = &sred[(uw * 2 + half) * 4];
            d[0] = a0; d[1] = a1; d[2] = a2; d[3] = a3;
        }
        __syncthreads();

        if (tid < 4) {
            const int rr = blockIdx.x * 4 + tid;
            const float* lo = &sred[(tid * 2 + 0) * 4];
            const float* hi = &sred[(tid * 2 + 1) * 4];
            const float gi = lo[0] + hi[0] + b_ih1[rr        ] + b_hh1[rr        ];
            const float gf = lo[1] + hi[1] + b_ih1[rr +     H] + b_hh1[rr +     H];
            const float gg = lo[2] + hi[2] + b_ih1[rr + 2 * H] + b_hh1[rr + 2 * H];
            const float go = lo[3] + hi[3] + b_ih1[rr + 3 * H] + b_hh1[rr + 3 * H];
            const float iv = sigmoidf_(gi);
            const float fv = sigmoidf_(gf);
            const float gv = tanhf(gg);
            const float ov = sigmoidf_(go);
            const float cn = fv * c1[rr] + iv * gv;
            g_h1n[rr] = ov * tanhf(cn);
        }
    } else {
        // ---------------- hh2 gate partials ----------------
        float* sh = sbuf;               // h2: 2048
        for (int i = tid; i < 2048; i += 256) sh[i] = h2[i];
        __syncthreads();

        const int r = (blockIdx.x - 512) * 4 + uw;
        const float4* sh4 = (const float4*)sh;
        const float4* w0 = (const float4*)(W_hh2 + (size_t)(r        ) * 2048);
        const float4* w1 = (const float4*)(W_hh2 + (size_t)(r +     H) * 2048);
        const float4* w2 = (const float4*)(W_hh2 + (size_t)(r + 2 * H) * 2048);
        const float4* w3 = (const float4*)(W_hh2 + (size_t)(r + 3 * H) * 2048);

        float a0 = 0.f, a1 = 0.f, a2 = 0.f, a3 = 0.f;
        dot4_range(w0, w1, w2, w3, sh4, half * 256, 256, lane, a0, a1, a2, a3);
        a0 = warp_sum(a0); a1 = warp_sum(a1); a2 = warp_sum(a2); a3 = warp_sum(a3);

        if (lane == 0) {
            float* d = &sred[(uw * 2 + half) * 4];
            d[0] = a0; d[1] = a1; d[2] = a2; d[3] = a3;
        }
        __syncthreads();

        if (tid < 4) {
            const int rr = (blockIdx.x - 512) * 4 + tid;
            const float* lo = &sred[(tid * 2 + 0) * 4];
            const float* hi = &sred[(tid * 2 + 1) * 4];
            g_gates2[rr        ] = lo[0] + hi[0] + b_ih2[rr        ] + b_hh2[rr        ];
            g_gates2[rr +     H] = lo[1] + hi[1] + b_ih2[rr +     H] + b_hh2[rr +     H];
            g_gates2[rr + 2 * H] = lo[2] + hi[2] + b_ih2[rr + 2 * H] + b_hh2[rr + 2 * H];
            g_gates2[rr + 3 * H] = lo[3] + hi[3] + b_ih2[rr + 3 * H] + b_hh2[rr + 3 * H];
        }
    }
}

// ---------------------------------------------------------------------------
// Stage B (512 blocks x 256 thr): finish layer 2, 2 warps per unit (K-split).
// ---------------------------------------------------------------------------
__global__ __launch_bounds__(256) void stageB_kernel(
    const float* __restrict__ W_ih2, const float* __restrict__ c2)
{
    __shared__ float sh[2048];
    __shared__ float sred[4 * 2 * 4];
    const int tid  = threadIdx.x;
    const int wid  = tid >> 5;
    const int lane = tid & 31;
    const int uw   = wid & 3;
    const int half = wid >> 2;

    for (int i = tid; i < 2048; i += 256) sh[i] = g_h1n[i];
    __syncthreads();

    const int r = blockIdx.x * 4 + uw;
    const float4* sh4 = (const float4*)sh;
    const float4* w0 = (const float4*)(W_ih2 + (size_t)(r        ) * 2048);
    const float4* w1 = (const float4*)(W_ih2 + (size_t)(r +     H) * 2048);
    const float4* w2 = (const float4*)(W_ih2 + (size_t)(r + 2 * H) * 2048);
    const float4* w3 = (const float4*)(W_ih2 + (size_t)(r + 3 * H) * 2048);

    float a0 = 0.f, a1 = 0.f, a2 = 0.f, a3 = 0.f;
    dot4_range(w0, w1, w2, w3, sh4, half * 256, 256, lane, a0, a1, a2, a3);
    a0 = warp_sum(a0); a1 = warp_sum(a1); a2 = warp_sum(a2); a3 = warp_sum(a3);

    if (lane == 0) {
        float* d = &sred[(uw * 2 + half) * 4];
        d[0] = a0; d[1] = a1; d[2] = a2; d[3] = a3;
    }
    __syncthreads();

    if (tid < 4) {
        const int rr = blockIdx.x * 4 + tid;
        const float* lo = &sred[(tid * 2 + 0) * 4];
        const float* hi = &sred[(tid * 2 + 1) * 4];
        const float gi = lo[0] + hi[0] + g_gates2[rr        ];
        const float gf = lo[1] + hi[1] + g_gates2[rr +     H];
        const float gg = lo[2] + hi[2] + g_gates2[rr + 2 * H];
        const float go = lo[3] + hi[3] + g_gates2[rr + 3 * H];
        const float iv = sigmoidf_(gi);
        const float fv = sigmoidf_(gf);
        const float gv = tanhf(gg);
        const float ov = sigmoidf_(go);
        const float cn = fv * c2[rr] + iv * gv;
        g_h2n[rr] = ov * tanhf(cn);
    }
}

// ---------------------------------------------------------------------------
// Persistent fused vocab kernel: GEMV logits + logsumexp + log-softmax output.
// Grid fully co-resident (592 blocks, <=4/SM); monotonic ticket barrier is
// replay-safe with no reset step.
// ---------------------------------------------------------------------------
__global__ __launch_bounds__(VTHR, 4) void vocab_fused_kernel(
    const float* __restrict__ W, const float* __restrict__ b,
    float* __restrict__ out)
{
    __shared__ float sh[2048];
    __shared__ float swm[8];
    __shared__ float sws[8];
    __shared__ float sred[256];

    const int tid  = threadIdx.x;
    const int wid  = tid >> 5;
    const int lane = tid & 31;
    const int wglob = blockIdx.x * 8 + wid;

    for (int i = tid; i < 2048; i += VTHR) sh[i] = g_h2n[i];
    __syncthreads();

    const float4* sh4 = (const float4*)sh;

    float m = -INFINITY, s = 0.0f;
    for (int it = 0; it < VITERS; it++) {
        const int row = wglob + it * VWARPS_TOTAL;
        if (row < VOC) {
            const float4* w4 = (const float4*)(W + (size_t)row * 2048);
            float a = 0.0f;
            #pragma unroll 8
            for (int j = lane; j < 512; j += 32) {
                float4 wv = __ldcs(&w4[j]); float4 hv = sh4[j];
                a += wv.x * hv.x + wv.y * hv.y + wv.z * hv.z + wv.w * hv.w;
            }
            a = warp_sum(a);
            const float v = a + __ldg(&b[row]);
            if (lane == 0) g_logits[row] = v;
            const float nm = fmaxf(m, v);
            s = s * expf(m - nm) + expf(v - nm);
            m = nm;
        }
    }
    if (lane == 0) { swm[wid] = m; sws[wid] = s; }
    __syncthreads();

    if (tid == 0) {
        float bm = -INFINITY;
        #pragma unroll
        for (int i = 0; i < 8; i++) bm = fmaxf(bm, swm[i]);
        float bs = 0.0f;
        #pragma unroll
        for (int i = 0; i < 8; i++)
            bs += (swm[i] == -INFINITY) ? 0.0f : sws[i] * expf(swm[i] - bm);
        g_pm[blockIdx.x] = bm;
        g_ps[blockIdx.x] = bs;
    }

    __threadfence();
    __syncthreads();
    if (tid == 0) {
        const unsigned long long my = atomicAdd(&g_ticket, 1ULL);
        const unsigned long long target = (my / VBLK + 1ULL) * VBLK;
        while (atomicAdd(&g_ticket, 0ULL) < target) { }
    }
    __syncthreads();
    __threadfence();

    float lm = -INFINITY;
    for (int i = tid; i < VBLK; i += VTHR) lm = fmaxf(lm, g_pm[i]);
    sred[tid] = lm;
    __syncthreads();
    for (int st = 128; st > 0; st >>= 1) {
        if (tid < st) sred[tid] = fmaxf(sred[tid], sred[tid + st]);
        __syncthreads();
    }
    const float M = sred[0];
    __syncthreads();

    float ls = 0.0f;
    for (int i = tid; i < VBLK; i += VTHR)
        ls += (g_pm[i] == -INFINITY) ? 0.0f : g_ps[i] * expf(g_pm[i] - M);
    sred[tid] = ls;
    __syncthreads();
    for (int st = 128; st > 0; st >>= 1) {
        if (tid < st) sred[tid] += sred[tid + st];
        __syncthreads();
    }
    const float shift = M + logf(sred[0]);

    for (int i = blockIdx.x * VTHR + tid; i < VOC; i += VBLK * VTHR)
        out[i] = g_logits[i] - shift;
}

// ---------------------------------------------------------------------------
extern "C" void kernel_launch(void* const* d_in, const int* in_sizes, int n_in,
                              void* d_out, int out_size)
{
    const float* x     = (const float*)d_in[0];
    const float* h1    = (const float*)d_in[1];
    const float* c1    = (const float*)d_in[2];
    const float* h2    = (const float*)d_in[3];
    const float* c2    = (const float*)d_in[4];
    const float* W_ih1 = (const float*)d_in[5];
    const float* W_hh1 = (const float*)d_in[6];
    const float* b_ih1 = (const float*)d_in[7];
    const float* b_hh1 = (const float*)d_in[8];
    const float* W_ih2 = (const float*)d_in[9];
    const float* W_hh2 = (const float*)d_in[10];
    const float* b_ih2 = (const float*)d_in[11];
    const float* b_hh2 = (const float*)d_in[12];
    const float* W_out = (const float*)d_in[13];
    const float* b_out = (const float*)d_in[14];
    float* out = (float*)d_out;

    // Stage A: layer 1 LSTM + layer 2 hh-partial (independent, concurrent)
    stageA_kernel<<<1024, 256>>>(W_ih1, W_hh1, b_ih1, b_hh1, x, h1, c1,
                                 W_hh2, b_ih2, b_hh2, h2);
    // Stage B: finish layer 2 (ih part + cell)
    stageB_kernel<<<512, 256>>>(W_ih2, c2);
    // Persistent fused vocab projection + logsumexp + log-softmax
    vocab_fused_kernel<<<VBLK, VTHR>>>(W_out, b_out, out);
}